// round 13
// baseline (speedup 1.0000x reference)
#include <cuda_runtime.h>
#include <cstdint>

// MMDNE fused kernel, R13 = R12 with k-chunk 16->32 (4 staging rounds).
// Staging q=tid&7: each warp-LDG.128 covers 4 rows x full 128B line (nL=4,
// halves L1 LDG wavefronts vs R12's 8-line pattern). XSTR=20 unchanged
// (LDSM conflict-free, STS <=2-way/phase). ldmatrix bases collapsed to one
// pointer + immediates to offset the larger staging-pointer set.

#define BB   50000
#define FF   128
#define EE   32
#define NNEG 10
#define ROWS 16
#define MV   416
#define NT   416
#define NRND 4               // staging rounds of k=32
#define XP   20              // x row stride in uint32 (64B data + 16B pad)
#define QSTR 34              // query-emb row stride (floats, even)
#define XLOB (MV * XP * 4)   // byte offset xhi -> xlo (33280)

struct SmemT {
    uint32_t wfrag[4096];    // ((ks*4+nt)*32+lane)*4 + {bh.x,bh.y,bl.x,bl.y}
    float bias[EE];
    float avec[2 * EE];
    float deltas[2];
    float sqq[96];           // query-row sqnorms
    float dots[96];          // 16 rows x 6 slots
    float wts[64];           // 16 rows x 4
    alignas(16) union {
        struct { uint32_t xhi[MV * XP]; uint32_t xlo[MV * XP]; } x;  // 66.6KB
        float embq[96 * QSTR];                                       // 13.1KB
    } u;
};

#define MMA_BF16(d, a0, a1, a2, a3, b0, b1)                                \
    asm volatile("mma.sync.aligned.m16n8k16.row.col.f32.bf16.bf16.f32 "    \
        "{%0,%1,%2,%3}, {%4,%5,%6,%7}, {%8,%9}, {%0,%1,%2,%3};"            \
        : "+f"(d[0]), "+f"(d[1]), "+f"(d[2]), "+f"(d[3])                   \
        : "r"(a0), "r"(a1), "r"(a2), "r"(a3), "r"(b0), "r"(b1))

#define LDSM4(r0, r1, r2, r3, addr)                                        \
    asm volatile("ldmatrix.sync.aligned.m8n8.x4.shared.b16 "               \
        "{%0,%1,%2,%3}, [%4];"                                             \
        : "=r"(r0), "=r"(r1), "=r"(r2), "=r"(r3) : "r"(addr))

__device__ __forceinline__ uint32_t pk_bf16(float hi, float lo) {
    uint32_t r;
    asm("cvt.rn.bf16x2.f32 %0, %1, %2;" : "=r"(r) : "f"(hi), "f"(lo));
    return r;
}

__global__ void __launch_bounds__(NT, 2) mmdne_kernel(
    const float* __restrict__ s_fts, const float* __restrict__ t_fts,
    const float* __restrict__ s_h_fts, const float* __restrict__ t_h_fts,
    const float* __restrict__ s_neg_fts, const float* __restrict__ t_neg_fts,
    const float* __restrict__ event_time,
    const float* __restrict__ s_h_times, const float* __restrict__ t_h_times,
    const float* __restrict__ s_h_mask, const float* __restrict__ t_h_mask,
    const float* __restrict__ W_fts, const float* __restrict__ b_fts,
    const float* __restrict__ a_vec,
    const float* __restrict__ delta_s, const float* __restrict__ delta_t,
    float* __restrict__ out)
{
    extern __shared__ char smem_raw[];
    SmemT& sm = *reinterpret_cast<SmemT*>(smem_raw);
    const int tid  = threadIdx.x;
    const int wid  = tid >> 5;
    const int lane = tid & 31;
    const int g    = lane >> 2;
    const int tg   = lane & 3;
    const int row_base = blockIdx.x * ROWS;   // grid exact: no clamping

    // ---- Phase 0: params + W -> bf16x2 hi/lo fragments (hi|lo interleaved) ----
    if (tid < EE)     sm.bias[tid] = b_fts[tid];
    if (tid < 2 * EE) sm.avec[tid] = a_vec[tid];
    if (tid == 0) { sm.deltas[0] = delta_s[0]; sm.deltas[1] = delta_t[0]; }
    for (int idx = tid; idx < 2048; idx += NT) {
        int ks  = idx >> 8;             // 0..7
        int rem = idx & 255;
        int nt  = rem >> 6;             // 0..3
        int l   = (rem >> 1) & 31;      // lane
        int rg2 = idx & 1;              // b0 / b1
        int gg = l >> 2, tt = l & 3;
        int k  = 16 * ks + 2 * tt + 8 * rg2;
        int e  = 8 * nt + gg;
        float w0 = W_fts[k * EE + e];
        float w1 = W_fts[(k + 1) * EE + e];
        uint32_t h = pk_bf16(w1, w0);
        float f0 = __uint_as_float(h << 16);
        float f1 = __uint_as_float(h & 0xFFFF0000u);
        int base = ((ks * 4 + nt) * 32 + l) * 4;
        sm.wfrag[base + rg2]     = h;
        sm.wfrag[base + 2 + rg2] = pk_bf16(w1 - f1, w0 - f0);
    }

    // ---- hoisted staging descriptors: 8 float4 per thread per round ----
    // idx = tid + i*NT -> m = (tid>>3) + 52*i (rows), q = tid&7 (k-quarter).
    const float* gptr[8];
    int sts0;
    {
        const int q = tid & 7;
        sts0 = (tid >> 3) * XP + 2 * q;       // +1040 per i (52 rows * 20)
#pragma unroll
        for (int i = 0; i < 8; ++i) {
            int m = (tid >> 3) + 52 * i;      // vector-row 0..415
            const float* gp;
            if (m < 16)       gp = s_fts     + (long)(row_base + m) * FF;
            else if (m < 32)  gp = t_fts     + (long)(row_base + m - 16) * FF;
            else if (m < 64)  gp = s_h_fts   + (long)(row_base * 2 + m - 32) * FF;
            else if (m < 96)  gp = t_h_fts   + (long)(row_base * 2 + m - 64) * FF;
            else if (m < 256) gp = s_neg_fts + (long)(row_base * 10 + m - 96) * FF;
            else              gp = t_neg_fts + (long)(row_base * 10 + m - 256) * FF;
            gptr[i] = gp + 4 * q;
        }
    }

    // ---- single ldmatrix base pointer (mt/kt/lo via immediates) ----
    uint32_t a_base;
    {
        uint32_t xhi_b = (uint32_t)__cvta_generic_to_shared(sm.u.x.xhi);
        int lrow = lane & 15;                 // row within m16 tile
        int lk   = (lane >> 4) << 2;          // +4 words for k8-15 matrices
        a_base = xhi_b + (uint32_t)(((32 * wid + lrow) * XP + lk) * 4);
        // + 1280*mt (16 rows) + 32*kt (8 words) + XLOB for lo
    }

    float acc[2][4][4];
#pragma unroll
    for (int mt = 0; mt < 2; ++mt)
#pragma unroll
        for (int nt = 0; nt < 4; ++nt)
#pragma unroll
            for (int j = 0; j < 4; ++j) acc[mt][nt][j] = 0.f;

    // ---- mainloop: 4 rounds of k=32 (2 MMA sub-chunks each) ----
#pragma unroll 1
    for (int c = 0; c < NRND; ++c) {
        __syncthreads();   // buffer free (also orders Phase0 before round 0)
#pragma unroll
        for (int i = 0; i < 8; ++i) {
            float4 v = *reinterpret_cast<const float4*>(gptr[i] + 32 * c);
            uint32_t h01 = pk_bf16(v.y, v.x);
            uint32_t h23 = pk_bf16(v.w, v.z);
            float f0 = __uint_as_float(h01 << 16);
            float f1 = __uint_as_float(h01 & 0xFFFF0000u);
            float f2 = __uint_as_float(h23 << 16);
            float f3 = __uint_as_float(h23 & 0xFFFF0000u);
            uint32_t l01 = pk_bf16(v.y - f1, v.x - f0);
            uint32_t l23 = pk_bf16(v.w - f3, v.z - f2);
            int o = sts0 + i * 1040;
            *reinterpret_cast<uint2*>(&sm.u.x.xhi[o]) = make_uint2(h01, h23);
            *reinterpret_cast<uint2*>(&sm.u.x.xlo[o]) = make_uint2(l01, l23);
        }
        __syncthreads();   // round visible

#pragma unroll
        for (int kt = 0; kt < 2; ++kt) {
#pragma unroll
            for (int mt = 0; mt < 2; ++mt) {
                uint32_t ah0, ah1, ah2, ah3, al0, al1, al2, al3;
                uint32_t ap = a_base + (uint32_t)(1280 * mt + 32 * kt);
                LDSM4(ah0, ah1, ah2, ah3, ap);
                LDSM4(al0, al1, al2, al3, ap + XLOB);
#pragma unroll
                for (int nt = 0; nt < 4; ++nt) {
                    uint4 w = *reinterpret_cast<const uint4*>(
                        &sm.wfrag[(((c * 2 + kt) * 4 + nt) * 32 + lane) * 4]);
                    MMA_BF16(acc[mt][nt], ah0, ah1, ah2, ah3, w.x, w.y);
                    MMA_BF16(acc[mt][nt], ah0, ah1, ah2, ah3, w.z, w.w);
                    MMA_BF16(acc[mt][nt], al0, al1, al2, al3, w.x, w.y);
                }
            }
        }
    }
    __syncthreads();   // xs consumed -> embq alias safe

    // ---- Epilogue A: fold bias, sqnorms; query warps -> smem ----
    float sqr[2][2];
#pragma unroll
    for (int mt = 0; mt < 2; ++mt) {
        float s1 = 0.f, s2 = 0.f;
#pragma unroll
        for (int nt = 0; nt < 4; ++nt) {
            const int col = nt * 8 + tg * 2;
            float b0 = sm.bias[col], b1v = sm.bias[col + 1];
            acc[mt][nt][0] += b0; acc[mt][nt][1] += b1v;
            acc[mt][nt][2] += b0; acc[mt][nt][3] += b1v;
            s1 += acc[mt][nt][0] * acc[mt][nt][0] + acc[mt][nt][1] * acc[mt][nt][1];
            s2 += acc[mt][nt][2] * acc[mt][nt][2] + acc[mt][nt][3] * acc[mt][nt][3];
        }
        s1 += __shfl_xor_sync(0xFFFFFFFFu, s1, 1); s1 += __shfl_xor_sync(0xFFFFFFFFu, s1, 2);
        s2 += __shfl_xor_sync(0xFFFFFFFFu, s2, 1); s2 += __shfl_xor_sync(0xFFFFFFFFu, s2, 2);
        sqr[mt][0] = s1; sqr[mt][1] = s2;
    }
    if (wid < 3) {
        const float* av = sm.avec + ((wid == 0) ? 0 : EE);
#pragma unroll
        for (int mt = 0; mt < 2; ++mt) {
            const int r1 = wid * 32 + mt * 16 + g;
            const int r2 = r1 + 8;
            float d1 = 0.f, d2 = 0.f;
#pragma unroll
            for (int nt = 0; nt < 4; ++nt) {
                const int col = nt * 8 + tg * 2;
                *reinterpret_cast<float2*>(&sm.u.embq[r1 * QSTR + col]) =
                    make_float2(acc[mt][nt][0], acc[mt][nt][1]);
                *reinterpret_cast<float2*>(&sm.u.embq[r2 * QSTR + col]) =
                    make_float2(acc[mt][nt][2], acc[mt][nt][3]);
                d1 += acc[mt][nt][0] * av[col] + acc[mt][nt][1] * av[col + 1];
                d2 += acc[mt][nt][2] * av[col] + acc[mt][nt][3] * av[col + 1];
            }
            d1 += __shfl_xor_sync(0xFFFFFFFFu, d1, 1); d1 += __shfl_xor_sync(0xFFFFFFFFu, d1, 2);
            d2 += __shfl_xor_sync(0xFFFFFFFFu, d2, 1); d2 += __shfl_xor_sync(0xFFFFFFFFu, d2, 2);
            if (tg == 0) {
                sm.sqq[r1] = sqr[mt][0];
                sm.sqq[r2] = sqr[mt][1];
                int mm = r1; float dd = d1;
#pragma unroll
                for (int rep = 0; rep < 2; ++rep) {
                    if (mm < 16)      sm.dots[mm * 6 + 0] = dd;
                    else if (mm < 32) sm.dots[(mm - 16) * 6 + 1] = dd;
                    else if (mm < 64) sm.dots[((mm - 32) >> 1) * 6 + 2 + ((mm - 32) & 1)] = dd;
                    else              sm.dots[((mm - 64) >> 1) * 6 + 4 + ((mm - 64) & 1)] = dd;
                    mm = r2; dd = d2;
                }
            }
        }
    }
    __syncthreads();

    // ---- Epilogue B: attention weights (16 threads) ----
    if (tid < ROWS) {
        const int r = tid;
        const int rg = row_base + r;
        const float ds = sm.deltas[0];
        const float dt = sm.deltas[1];
        const float et = event_time[rg];

        float dts0 = fabsf(et - s_h_times[rg * 2 + 0]);
        float dts1 = fabsf(et - s_h_times[rg * 2 + 1]);
        float sc0 = sm.dots[r * 6 + 0] + sm.dots[r * 6 + 2];
        float sc1 = sm.dots[r * 6 + 0] + sm.dots[r * 6 + 3];
        float sim0 = expf(-ds * dts0) * sc0; sim0 = (sim0 > 0.f) ? sim0 : 0.2f * sim0;
        float sim1 = expf(-ds * dts1) * sc1; sim1 = (sim1 > 0.f) ? sim1 : 0.2f * sim1;
        float mx = fmaxf(sim0, sim1);
        float e0 = expf(sim0 - mx), e1 = expf(sim1 - mx);
        float inv = 1.f / (e0 + e1);
        sm.wts[r * 4 + 0] = e0 * inv * expf(ds * dts0) * s_h_mask[rg * 2 + 0];
        sm.wts[r * 4 + 1] = e1 * inv * expf(ds * dts1) * s_h_mask[rg * 2 + 1];

        float dtt0 = fabsf(et - t_h_times[rg * 2 + 0]);
        float dtt1 = fabsf(et - t_h_times[rg * 2 + 1]);
        float tc0 = sm.dots[r * 6 + 1] + sm.dots[r * 6 + 4];
        float tc1 = sm.dots[r * 6 + 1] + sm.dots[r * 6 + 5];
        float tm0 = expf(-dt * dtt0) * tc0; tm0 = (tm0 > 0.f) ? tm0 : 0.2f * tm0;
        float tm1 = expf(-dt * dtt1) * tc1; tm1 = (tm1 > 0.f) ? tm1 : 0.2f * tm1;
        float mx2 = fmaxf(tm0, tm1);
        float f0 = expf(tm0 - mx2), f1 = expf(tm1 - mx2);
        float inv2 = 1.f / (f0 + f1);
        sm.wts[r * 4 + 2] = f0 * inv2 * expf(dt * dtt0) * t_h_mask[rg * 2 + 0];
        sm.wts[r * 4 + 3] = f1 * inv2 * expf(dt * dtt1) * t_h_mask[rg * 2 + 1];
    }
    __syncthreads();

    // ---- Epilogue C ----
    // p_lambda from query smem (warp 0, 16 lanes)
    if (wid == 0 && lane < ROWS) {
        const int r = lane;
        const float* es  = sm.u.embq + r * QSTR;
        const float* etb = sm.u.embq + (16 + r) * QSTR;
        const float* h0  = sm.u.embq + (32 + 2 * r) * QSTR;
        const float* h1  = sm.u.embq + (33 + 2 * r) * QSTR;
        float pm = 0.f, pa0 = 0.f, pa1 = 0.f;
#pragma unroll
        for (int e = 0; e < EE; ++e) {
            float te = etb[e];
            float d0 = es[e] - te; pm  -= d0 * d0;
            float d1 = h0[e] - te; pa0 -= d1 * d1;
            float d2 = h1[e] - te; pa1 -= d2 * d2;
        }
        out[row_base + r] = pm + sm.wts[r * 4 + 0] * pa0 + sm.wts[r * 4 + 1] * pa1;
    }
    // n_lambda from register accumulators (warps 3..12)
    if (wid >= 3) {
#pragma unroll
        for (int mt = 0; mt < 2; ++mt) {
#pragma unroll
            for (int half = 0; half < 2; ++half) {
                const int m = 32 * wid + 16 * mt + 8 * half + g;
                const bool isT = (m >= 256);
                const int mm = isT ? (m - 256) : (m - 96);
                const int rr = mm / 10;
                const int n  = mm - 10 * rr;
                const int qa_row  = isT ? rr : (16 + rr);
                const int qh0_row = isT ? (32 + 2 * rr) : (64 + 2 * rr);
                const float* qa  = sm.u.embq + qa_row * QSTR;
                const float* qh0 = sm.u.embq + qh0_row * QSTR;
                const float* qh1 = qh0 + QSTR;
                float da = 0.f, d0 = 0.f, d1 = 0.f;
#pragma unroll
                for (int nt = 0; nt < 4; ++nt) {
                    const int col = nt * 8 + tg * 2;
                    float e0 = acc[mt][nt][2 * half];
                    float e1 = acc[mt][nt][2 * half + 1];
                    da += e0 * qa[col]  + e1 * qa[col + 1];
                    d0 += e0 * qh0[col] + e1 * qh0[col + 1];
                    d1 += e0 * qh1[col] + e1 * qh1[col + 1];
                }
                da += __shfl_xor_sync(0xFFFFFFFFu, da, 1); da += __shfl_xor_sync(0xFFFFFFFFu, da, 2);
                d0 += __shfl_xor_sync(0xFFFFFFFFu, d0, 1); d0 += __shfl_xor_sync(0xFFFFFFFFu, d0, 2);
                d1 += __shfl_xor_sync(0xFFFFFFFFu, d1, 1); d1 += __shfl_xor_sync(0xFFFFFFFFu, d1, 2);
                if (tg == 0) {
                    float sqn  = sqr[mt][half];
                    float wv0  = sm.wts[4 * rr + (isT ? 0 : 2)];
                    float wv1  = sm.wts[4 * rr + (isT ? 1 : 3)];
                    float nmu  = -(sm.sqq[qa_row]      + sqn - 2.f * da);
                    float na0  = -(sm.sqq[qh0_row]     + sqn - 2.f * d0);
                    float na1  = -(sm.sqq[qh0_row + 1] + sqn - 2.f * d1);
                    long off = isT ? (long)BB : (long)BB * 11;
                    out[off + (long)(row_base + rr) * NNEG + n] =
                        nmu + wv0 * na0 + wv1 * na1;
                }
            }
        }
    }
}

extern "C" void kernel_launch(void* const* d_in, const int* in_sizes, int n_in,
                              void* d_out, int out_size)
{
    const float* s_fts      = (const float*)d_in[0];
    const float* t_fts      = (const float*)d_in[1];
    const float* s_h_fts    = (const float*)d_in[2];
    const float* t_h_fts    = (const float*)d_in[3];
    const float* s_neg_fts  = (const float*)d_in[4];
    const float* t_neg_fts  = (const float*)d_in[5];
    const float* event_time = (const float*)d_in[6];
    const float* s_h_times  = (const float*)d_in[7];
    const float* t_h_times  = (const float*)d_in[8];
    const float* s_h_mask   = (const float*)d_in[9];
    const float* t_h_mask   = (const float*)d_in[10];
    const float* W_fts      = (const float*)d_in[11];
    const float* b_fts      = (const float*)d_in[12];
    const float* a_vec      = (const float*)d_in[13];
    const float* delta_s    = (const float*)d_in[14];
    const float* delta_t    = (const float*)d_in[15];
    float* out = (float*)d_out;

    const int smem_bytes = (int)sizeof(SmemT);
    cudaFuncSetAttribute(mmdne_kernel,
                         cudaFuncAttributeMaxDynamicSharedMemorySize, smem_bytes);

    const int nblocks = BB / ROWS;   // 3125 exact
    mmdne_kernel<<<nblocks, NT, smem_bytes>>>(
        s_fts, t_fts, s_h_fts, t_h_fts, s_neg_fts, t_neg_fts,
        event_time, s_h_times, t_h_times, s_h_mask, t_h_mask,
        W_fts, b_fts, a_vec, delta_s, delta_t, out);
}

// round 14
// speedup vs baseline: 1.0261x; 1.0261x over previous
#include <cuda_runtime.h>
#include <cstdint>

// MMDNE fused kernel, R14 = R13 with:
//  - W-fragment loads hoisted out of the mt loop (16 -> 8 LDS.128/warp/round)
//  - round loop fully unrolled (immediate offsets, less ALU index math)
// Base: bf16 3-term split m16n8k16, chunk-32 staging (line-covering LDG),
// register-resident neg epilogue, __launch_bounds__(416,2).

#define BB   50000
#define FF   128
#define EE   32
#define NNEG 10
#define ROWS 16
#define MV   416
#define NT   416
#define NRND 4               // staging rounds of k=32
#define XP   20              // x row stride in uint32 (64B data + 16B pad)
#define QSTR 34              // query-emb row stride (floats, even)
#define XLOB (MV * XP * 4)   // byte offset xhi -> xlo (33280)

struct SmemT {
    uint32_t wfrag[4096];    // ((ks*4+nt)*32+lane)*4 + {bh.x,bh.y,bl.x,bl.y}
    float bias[EE];
    float avec[2 * EE];
    float deltas[2];
    float sqq[96];           // query-row sqnorms
    float dots[96];          // 16 rows x 6 slots
    float wts[64];           // 16 rows x 4
    alignas(16) union {
        struct { uint32_t xhi[MV * XP]; uint32_t xlo[MV * XP]; } x;  // 66.6KB
        float embq[96 * QSTR];                                       // 13.1KB
    } u;
};

#define MMA_BF16(d, a0, a1, a2, a3, b0, b1)                                \
    asm volatile("mma.sync.aligned.m16n8k16.row.col.f32.bf16.bf16.f32 "    \
        "{%0,%1,%2,%3}, {%4,%5,%6,%7}, {%8,%9}, {%0,%1,%2,%3};"            \
        : "+f"(d[0]), "+f"(d[1]), "+f"(d[2]), "+f"(d[3])                   \
        : "r"(a0), "r"(a1), "r"(a2), "r"(a3), "r"(b0), "r"(b1))

#define LDSM4(r0, r1, r2, r3, addr)                                        \
    asm volatile("ldmatrix.sync.aligned.m8n8.x4.shared.b16 "               \
        "{%0,%1,%2,%3}, [%4];"                                             \
        : "=r"(r0), "=r"(r1), "=r"(r2), "=r"(r3) : "r"(addr))

__device__ __forceinline__ uint32_t pk_bf16(float hi, float lo) {
    uint32_t r;
    asm("cvt.rn.bf16x2.f32 %0, %1, %2;" : "=r"(r) : "f"(hi), "f"(lo));
    return r;
}

__global__ void __launch_bounds__(NT, 2) mmdne_kernel(
    const float* __restrict__ s_fts, const float* __restrict__ t_fts,
    const float* __restrict__ s_h_fts, const float* __restrict__ t_h_fts,
    const float* __restrict__ s_neg_fts, const float* __restrict__ t_neg_fts,
    const float* __restrict__ event_time,
    const float* __restrict__ s_h_times, const float* __restrict__ t_h_times,
    const float* __restrict__ s_h_mask, const float* __restrict__ t_h_mask,
    const float* __restrict__ W_fts, const float* __restrict__ b_fts,
    const float* __restrict__ a_vec,
    const float* __restrict__ delta_s, const float* __restrict__ delta_t,
    float* __restrict__ out)
{
    extern __shared__ char smem_raw[];
    SmemT& sm = *reinterpret_cast<SmemT*>(smem_raw);
    const int tid  = threadIdx.x;
    const int wid  = tid >> 5;
    const int lane = tid & 31;
    const int g    = lane >> 2;
    const int tg   = lane & 3;
    const int row_base = blockIdx.x * ROWS;   // grid exact: no clamping

    // ---- Phase 0: params + W -> bf16x2 hi/lo fragments (hi|lo interleaved) ----
    if (tid < EE)     sm.bias[tid] = b_fts[tid];
    if (tid < 2 * EE) sm.avec[tid] = a_vec[tid];
    if (tid == 0) { sm.deltas[0] = delta_s[0]; sm.deltas[1] = delta_t[0]; }
    for (int idx = tid; idx < 2048; idx += NT) {
        int ks  = idx >> 8;             // 0..7
        int rem = idx & 255;
        int nt  = rem >> 6;             // 0..3
        int l   = (rem >> 1) & 31;      // lane
        int rg2 = idx & 1;              // b0 / b1
        int gg = l >> 2, tt = l & 3;
        int k  = 16 * ks + 2 * tt + 8 * rg2;
        int e  = 8 * nt + gg;
        float w0 = W_fts[k * EE + e];
        float w1 = W_fts[(k + 1) * EE + e];
        uint32_t h = pk_bf16(w1, w0);
        float f0 = __uint_as_float(h << 16);
        float f1 = __uint_as_float(h & 0xFFFF0000u);
        int base = ((ks * 4 + nt) * 32 + l) * 4;
        sm.wfrag[base + rg2]     = h;
        sm.wfrag[base + 2 + rg2] = pk_bf16(w1 - f1, w0 - f0);
    }

    // ---- hoisted staging descriptors: 8 float4 per thread per round ----
    const float* gptr[8];
    int sts0;
    {
        const int q = tid & 7;
        sts0 = (tid >> 3) * XP + 2 * q;       // +1040 per i (52 rows * 20)
#pragma unroll
        for (int i = 0; i < 8; ++i) {
            int m = (tid >> 3) + 52 * i;      // vector-row 0..415
            const float* gp;
            if (m < 16)       gp = s_fts     + (long)(row_base + m) * FF;
            else if (m < 32)  gp = t_fts     + (long)(row_base + m - 16) * FF;
            else if (m < 64)  gp = s_h_fts   + (long)(row_base * 2 + m - 32) * FF;
            else if (m < 96)  gp = t_h_fts   + (long)(row_base * 2 + m - 64) * FF;
            else if (m < 256) gp = s_neg_fts + (long)(row_base * 10 + m - 96) * FF;
            else              gp = t_neg_fts + (long)(row_base * 10 + m - 256) * FF;
            gptr[i] = gp + 4 * q;
        }
    }

    // ---- single ldmatrix base pointer (mt/kt/lo via immediates) ----
    uint32_t a_base;
    {
        uint32_t xhi_b = (uint32_t)__cvta_generic_to_shared(sm.u.x.xhi);
        int lrow = lane & 15;                 // row within m16 tile
        int lk   = (lane >> 4) << 2;          // +4 words for k8-15 matrices
        a_base = xhi_b + (uint32_t)(((32 * wid + lrow) * XP + lk) * 4);
    }

    float acc[2][4][4];
#pragma unroll
    for (int mt = 0; mt < 2; ++mt)
#pragma unroll
        for (int nt = 0; nt < 4; ++nt)
#pragma unroll
            for (int j = 0; j < 4; ++j) acc[mt][nt][j] = 0.f;

    // ---- mainloop: 4 rounds of k=32 (fully unrolled) ----
#pragma unroll
    for (int c = 0; c < NRND; ++c) {
        __syncthreads();   // buffer free (also orders Phase0 before round 0)
#pragma unroll
        for (int i = 0; i < 8; ++i) {
            float4 v = *reinterpret_cast<const float4*>(gptr[i] + 32 * c);
            uint32_t h01 = pk_bf16(v.y, v.x);
            uint32_t h23 = pk_bf16(v.w, v.z);
            float f0 = __uint_as_float(h01 << 16);
            float f1 = __uint_as_float(h01 & 0xFFFF0000u);
            float f2 = __uint_as_float(h23 << 16);
            float f3 = __uint_as_float(h23 & 0xFFFF0000u);
            uint32_t l01 = pk_bf16(v.y - f1, v.x - f0);
            uint32_t l23 = pk_bf16(v.w - f3, v.z - f2);
            int o = sts0 + i * 1040;
            *reinterpret_cast<uint2*>(&sm.u.x.xhi[o]) = make_uint2(h01, h23);
            *reinterpret_cast<uint2*>(&sm.u.x.xlo[o]) = make_uint2(l01, l23);
        }
        __syncthreads();   // round visible

#pragma unroll
        for (int kt = 0; kt < 2; ++kt) {
            // LDSM all A tiles for this kt first (hi/lo x mt)
            uint32_t ah[2][4], al[2][4];
#pragma unroll
            for (int mt = 0; mt < 2; ++mt) {
                uint32_t ap = a_base + (uint32_t)(1280 * mt + 32 * kt);
                LDSM4(ah[mt][0], ah[mt][1], ah[mt][2], ah[mt][3], ap);
                LDSM4(al[mt][0], al[mt][1], al[mt][2], al[mt][3], ap + XLOB);
            }
            // one w load per nt, reused across both mt tiles
#pragma unroll
            for (int nt = 0; nt < 4; ++nt) {
                uint4 w = *reinterpret_cast<const uint4*>(
                    &sm.wfrag[(((c * 2 + kt) * 4 + nt) * 32 + lane) * 4]);
#pragma unroll
                for (int mt = 0; mt < 2; ++mt) {
                    MMA_BF16(acc[mt][nt], ah[mt][0], ah[mt][1], ah[mt][2], ah[mt][3], w.x, w.y);
                    MMA_BF16(acc[mt][nt], ah[mt][0], ah[mt][1], ah[mt][2], ah[mt][3], w.z, w.w);
                    MMA_BF16(acc[mt][nt], al[mt][0], al[mt][1], al[mt][2], al[mt][3], w.x, w.y);
                }
            }
        }
    }
    __syncthreads();   // xs consumed -> embq alias safe

    // ---- Epilogue A: fold bias, sqnorms; query warps -> smem ----
    float sqr[2][2];
#pragma unroll
    for (int mt = 0; mt < 2; ++mt) {
        float s1 = 0.f, s2 = 0.f;
#pragma unroll
        for (int nt = 0; nt < 4; ++nt) {
            const int col = nt * 8 + tg * 2;
            float b0 = sm.bias[col], b1v = sm.bias[col + 1];
            acc[mt][nt][0] += b0; acc[mt][nt][1] += b1v;
            acc[mt][nt][2] += b0; acc[mt][nt][3] += b1v;
            s1 += acc[mt][nt][0] * acc[mt][nt][0] + acc[mt][nt][1] * acc[mt][nt][1];
            s2 += acc[mt][nt][2] * acc[mt][nt][2] + acc[mt][nt][3] * acc[mt][nt][3];
        }
        s1 += __shfl_xor_sync(0xFFFFFFFFu, s1, 1); s1 += __shfl_xor_sync(0xFFFFFFFFu, s1, 2);
        s2 += __shfl_xor_sync(0xFFFFFFFFu, s2, 1); s2 += __shfl_xor_sync(0xFFFFFFFFu, s2, 2);
        sqr[mt][0] = s1; sqr[mt][1] = s2;
    }
    if (wid < 3) {
        const float* av = sm.avec + ((wid == 0) ? 0 : EE);
#pragma unroll
        for (int mt = 0; mt < 2; ++mt) {
            const int r1 = wid * 32 + mt * 16 + g;
            const int r2 = r1 + 8;
            float d1 = 0.f, d2 = 0.f;
#pragma unroll
            for (int nt = 0; nt < 4; ++nt) {
                const int col = nt * 8 + tg * 2;
                *reinterpret_cast<float2*>(&sm.u.embq[r1 * QSTR + col]) =
                    make_float2(acc[mt][nt][0], acc[mt][nt][1]);
                *reinterpret_cast<float2*>(&sm.u.embq[r2 * QSTR + col]) =
                    make_float2(acc[mt][nt][2], acc[mt][nt][3]);
                d1 += acc[mt][nt][0] * av[col] + acc[mt][nt][1] * av[col + 1];
                d2 += acc[mt][nt][2] * av[col] + acc[mt][nt][3] * av[col + 1];
            }
            d1 += __shfl_xor_sync(0xFFFFFFFFu, d1, 1); d1 += __shfl_xor_sync(0xFFFFFFFFu, d1, 2);
            d2 += __shfl_xor_sync(0xFFFFFFFFu, d2, 1); d2 += __shfl_xor_sync(0xFFFFFFFFu, d2, 2);
            if (tg == 0) {
                sm.sqq[r1] = sqr[mt][0];
                sm.sqq[r2] = sqr[mt][1];
                int mm = r1; float dd = d1;
#pragma unroll
                for (int rep = 0; rep < 2; ++rep) {
                    if (mm < 16)      sm.dots[mm * 6 + 0] = dd;
                    else if (mm < 32) sm.dots[(mm - 16) * 6 + 1] = dd;
                    else if (mm < 64) sm.dots[((mm - 32) >> 1) * 6 + 2 + ((mm - 32) & 1)] = dd;
                    else              sm.dots[((mm - 64) >> 1) * 6 + 4 + ((mm - 64) & 1)] = dd;
                    mm = r2; dd = d2;
                }
            }
        }
    }
    __syncthreads();

    // ---- Epilogue B: attention weights (16 threads) ----
    if (tid < ROWS) {
        const int r = tid;
        const int rg = row_base + r;
        const float ds = sm.deltas[0];
        const float dt = sm.deltas[1];
        const float et = event_time[rg];

        float dts0 = fabsf(et - s_h_times[rg * 2 + 0]);
        float dts1 = fabsf(et - s_h_times[rg * 2 + 1]);
        float sc0 = sm.dots[r * 6 + 0] + sm.dots[r * 6 + 2];
        float sc1 = sm.dots[r * 6 + 0] + sm.dots[r * 6 + 3];
        float sim0 = expf(-ds * dts0) * sc0; sim0 = (sim0 > 0.f) ? sim0 : 0.2f * sim0;
        float sim1 = expf(-ds * dts1) * sc1; sim1 = (sim1 > 0.f) ? sim1 : 0.2f * sim1;
        float mx = fmaxf(sim0, sim1);
        float e0 = expf(sim0 - mx), e1 = expf(sim1 - mx);
        float inv = 1.f / (e0 + e1);
        sm.wts[r * 4 + 0] = e0 * inv * expf(ds * dts0) * s_h_mask[rg * 2 + 0];
        sm.wts[r * 4 + 1] = e1 * inv * expf(ds * dts1) * s_h_mask[rg * 2 + 1];

        float dtt0 = fabsf(et - t_h_times[rg * 2 + 0]);
        float dtt1 = fabsf(et - t_h_times[rg * 2 + 1]);
        float tc0 = sm.dots[r * 6 + 1] + sm.dots[r * 6 + 4];
        float tc1 = sm.dots[r * 6 + 1] + sm.dots[r * 6 + 5];
        float tm0 = expf(-dt * dtt0) * tc0; tm0 = (tm0 > 0.f) ? tm0 : 0.2f * tm0;
        float tm1 = expf(-dt * dtt1) * tc1; tm1 = (tm1 > 0.f) ? tm1 : 0.2f * tm1;
        float mx2 = fmaxf(tm0, tm1);
        float f0 = expf(tm0 - mx2), f1 = expf(tm1 - mx2);
        float inv2 = 1.f / (f0 + f1);
        sm.wts[r * 4 + 2] = f0 * inv2 * expf(dt * dtt0) * t_h_mask[rg * 2 + 0];
        sm.wts[r * 4 + 3] = f1 * inv2 * expf(dt * dtt1) * t_h_mask[rg * 2 + 1];
    }
    __syncthreads();

    // ---- Epilogue C ----
    // p_lambda from query smem (warp 0, 16 lanes)
    if (wid == 0 && lane < ROWS) {
        const int r = lane;
        const float* es  = sm.u.embq + r * QSTR;
        const float* etb = sm.u.embq + (16 + r) * QSTR;
        const float* h0  = sm.u.embq + (32 + 2 * r) * QSTR;
        const float* h1  = sm.u.embq + (33 + 2 * r) * QSTR;
        float pm = 0.f, pa0 = 0.f, pa1 = 0.f;
#pragma unroll
        for (int e = 0; e < EE; ++e) {
            float te = etb[e];
            float d0 = es[e] - te; pm  -= d0 * d0;
            float d1 = h0[e] - te; pa0 -= d1 * d1;
            float d2 = h1[e] - te; pa1 -= d2 * d2;
        }
        out[row_base + r] = pm + sm.wts[r * 4 + 0] * pa0 + sm.wts[r * 4 + 1] * pa1;
    }
    // n_lambda from register accumulators (warps 3..12)
    if (wid >= 3) {
#pragma unroll
        for (int mt = 0; mt < 2; ++mt) {
#pragma unroll
            for (int half = 0; half < 2; ++half) {
                const int m = 32 * wid + 16 * mt + 8 * half + g;
                const bool isT = (m >= 256);
                const int mm = isT ? (m - 256) : (m - 96);
                const int rr = mm / 10;
                const int n  = mm - 10 * rr;
                const int qa_row  = isT ? rr : (16 + rr);
                const int qh0_row = isT ? (32 + 2 * rr) : (64 + 2 * rr);
                const float* qa  = sm.u.embq + qa_row * QSTR;
                const float* qh0 = sm.u.embq + qh0_row * QSTR;
                const float* qh1 = qh0 + QSTR;
                float da = 0.f, d0 = 0.f, d1 = 0.f;
#pragma unroll
                for (int nt = 0; nt < 4; ++nt) {
                    const int col = nt * 8 + tg * 2;
                    float e0 = acc[mt][nt][2 * half];
                    float e1 = acc[mt][nt][2 * half + 1];
                    da += e0 * qa[col]  + e1 * qa[col + 1];
                    d0 += e0 * qh0[col] + e1 * qh0[col + 1];
                    d1 += e0 * qh1[col] + e1 * qh1[col + 1];
                }
                da += __shfl_xor_sync(0xFFFFFFFFu, da, 1); da += __shfl_xor_sync(0xFFFFFFFFu, da, 2);
                d0 += __shfl_xor_sync(0xFFFFFFFFu, d0, 1); d0 += __shfl_xor_sync(0xFFFFFFFFu, d0, 2);
                d1 += __shfl_xor_sync(0xFFFFFFFFu, d1, 1); d1 += __shfl_xor_sync(0xFFFFFFFFu, d1, 2);
                if (tg == 0) {
                    float sqn  = sqr[mt][half];
                    float wv0  = sm.wts[4 * rr + (isT ? 0 : 2)];
                    float wv1  = sm.wts[4 * rr + (isT ? 1 : 3)];
                    float nmu  = -(sm.sqq[qa_row]      + sqn - 2.f * da);
                    float na0  = -(sm.sqq[qh0_row]     + sqn - 2.f * d0);
                    float na1  = -(sm.sqq[qh0_row + 1] + sqn - 2.f * d1);
                    long off = isT ? (long)BB : (long)BB * 11;
                    out[off + (long)(row_base + rr) * NNEG + n] =
                        nmu + wv0 * na0 + wv1 * na1;
                }
            }
        }
    }
}

extern "C" void kernel_launch(void* const* d_in, const int* in_sizes, int n_in,
                              void* d_out, int out_size)
{
    const float* s_fts      = (const float*)d_in[0];
    const float* t_fts      = (const float*)d_in[1];
    const float* s_h_fts    = (const float*)d_in[2];
    const float* t_h_fts    = (const float*)d_in[3];
    const float* s_neg_fts  = (const float*)d_in[4];
    const float* t_neg_fts  = (const float*)d_in[5];
    const float* event_time = (const float*)d_in[6];
    const float* s_h_times  = (const float*)d_in[7];
    const float* t_h_times  = (const float*)d_in[8];
    const float* s_h_mask   = (const float*)d_in[9];
    const float* t_h_mask   = (const float*)d_in[10];
    const float* W_fts      = (const float*)d_in[11];
    const float* b_fts      = (const float*)d_in[12];
    const float* a_vec      = (const float*)d_in[13];
    const float* delta_s    = (const float*)d_in[14];
    const float* delta_t    = (const float*)d_in[15];
    float* out = (float*)d_out;

    const int smem_bytes = (int)sizeof(SmemT);
    cudaFuncSetAttribute(mmdne_kernel,
                         cudaFuncAttributeMaxDynamicSharedMemorySize, smem_bytes);

    const int nblocks = BB / ROWS;   // 3125 exact
    mmdne_kernel<<<nblocks, NT, smem_bytes>>>(
        s_fts, t_fts, s_h_fts, t_h_fts, s_neg_fts, t_neg_fts,
        event_time, s_h_times, t_h_times, s_h_mask, t_h_mask,
        W_fts, b_fts, a_vec, delta_s, delta_t, out);
}